// round 1
// baseline (speedup 1.0000x reference)
#include <cuda_runtime.h>
#include <math_constants.h>

#define Bn 16
#define Sn 2048
#define Dn 1024
#define Hn 64

// ---------------- scratch (device globals; no allocations allowed) ----------
__device__ float g_h[(size_t)Bn * Sn * Hn];        //   8 MB  relu(query@w1+b1)
__device__ float g_q[(size_t)Bn * Sn * Dn];        // 134 MB  query proj
__device__ float g_k[(size_t)Bn * Sn * Dn];        // 134 MB  key proj
__device__ float g_logits[(size_t)Bn * Sn * Sn];   // 256 MB  logits -> attention (in-place)
__device__ float g_w2t[Sn * Hn];                   // 512 KB  w2 transposed [S,H]

// ---------------- 128x128x8 register-tiled SGEMM (NN), optional bias/relu ---
#define MMA_STEP()                                                             \
    _Pragma("unroll")                                                          \
    for (int kk = 0; kk < 8; ++kk) {                                           \
        float a[8], bb[8];                                                     \
        *(float4*)&a[0]  = *(const float4*)&As[kk][ty * 8];                    \
        *(float4*)&a[4]  = *(const float4*)&As[kk][ty * 8 + 4];                \
        *(float4*)&bb[0] = *(const float4*)&Bs[kk][tx * 8];                    \
        *(float4*)&bb[4] = *(const float4*)&Bs[kk][tx * 8 + 4];                \
        _Pragma("unroll") for (int i = 0; i < 8; ++i)                          \
            _Pragma("unroll") for (int j = 0; j < 8; ++j)                      \
                acc[i][j] += a[i] * bb[j];                                     \
    }

template <bool RELU, bool BIAS>
__global__ void __launch_bounds__(256)
sgemm_nn(const float* __restrict__ A, const float* __restrict__ B,
         const float* __restrict__ bias, float* __restrict__ C,
         int M, int N, int K,
         long long strideA, long long strideB, long long strideC)
{
    A += (size_t)blockIdx.z * strideA;
    B += (size_t)blockIdx.z * strideB;
    C += (size_t)blockIdx.z * strideC;

    __shared__ float As[8][128];
    __shared__ float Bs[8][128];

    const int tid = threadIdx.x;
    const int bm = blockIdx.y * 128;
    const int bn = blockIdx.x * 128;

    // A tile loader: 128 rows x 8 k, 2 threads per row, float4 each
    const int a_row = tid >> 1;
    const int a_k   = (tid & 1) * 4;
    // B tile loader: 8 rows x 128 n, 32 threads per row, float4 each
    const int b_row = tid >> 5;
    const int b_col = (tid & 31) * 4;

    const int tx = tid & 15;
    const int ty = tid >> 4;

    float acc[8][8];
#pragma unroll
    for (int i = 0; i < 8; ++i)
#pragma unroll
        for (int j = 0; j < 8; ++j) acc[i][j] = 0.f;

    for (int k0 = 0; k0 < K; k0 += 8) {
        float4 av = *(const float4*)(A + (size_t)(bm + a_row) * K + k0 + a_k);
        As[a_k + 0][a_row] = av.x;
        As[a_k + 1][a_row] = av.y;
        As[a_k + 2][a_row] = av.z;
        As[a_k + 3][a_row] = av.w;

        float4 bv = make_float4(0.f, 0.f, 0.f, 0.f);
        const int bcol = bn + b_col;
        if (bcol < N)
            bv = *(const float4*)(B + (size_t)(k0 + b_row) * N + bcol);
        *(float4*)&Bs[b_row][b_col] = bv;

        __syncthreads();
        MMA_STEP();
        __syncthreads();
    }

#pragma unroll
    for (int i = 0; i < 8; ++i) {
        const int row = bm + ty * 8 + i;
#pragma unroll
        for (int j = 0; j < 8; ++j) {
            const int col = bn + tx * 8 + j;
            if (col < N) {
                float v = acc[i][j];
                if (BIAS) v += bias[col];
                if (RELU) v = fmaxf(v, 0.f);
                C[(size_t)row * N + col] = v;
            }
        }
    }
}

// ---------------- energy kernel: logits = q@k^T + h@w2t^T + b2 (per batch) --
__global__ void __launch_bounds__(256)
energy_kernel(const float* __restrict__ q, const float* __restrict__ k,
              const float* __restrict__ h, const float* __restrict__ w2t,
              const float* __restrict__ b2, float* __restrict__ out)
{
    const int b = blockIdx.z;
    const float* Aq = q + (size_t)b * Sn * Dn;
    const float* Bk = k + (size_t)b * Sn * Dn;
    const float* Ah = h + (size_t)b * Sn * Hn;
    float* C = out + (size_t)b * Sn * Sn;

    __shared__ float As[8][128];
    __shared__ float Bs[8][128];

    const int tid = threadIdx.x;
    const int bm = blockIdx.y * 128;
    const int bn = blockIdx.x * 128;

    const int lrow = tid >> 1;        // tile row (for both A and B in NT form)
    const int lk   = (tid & 1) * 4;   // k offset within 8-chunk

    const int tx = tid & 15;
    const int ty = tid >> 4;

    float acc[8][8];
#pragma unroll
    for (int i = 0; i < 8; ++i)
#pragma unroll
        for (int j = 0; j < 8; ++j) acc[i][j] = 0.f;

    // phase 1: K = D = 1024, both operands row-major [rows, K]
    for (int k0 = 0; k0 < Dn; k0 += 8) {
        float4 av = *(const float4*)(Aq + (size_t)(bm + lrow) * Dn + k0 + lk);
        float4 bv = *(const float4*)(Bk + (size_t)(bn + lrow) * Dn + k0 + lk);
        As[lk + 0][lrow] = av.x; As[lk + 1][lrow] = av.y;
        As[lk + 2][lrow] = av.z; As[lk + 3][lrow] = av.w;
        Bs[lk + 0][lrow] = bv.x; Bs[lk + 1][lrow] = bv.y;
        Bs[lk + 2][lrow] = bv.z; Bs[lk + 3][lrow] = bv.w;
        __syncthreads();
        MMA_STEP();
        __syncthreads();
    }

    // phase 2: K = H = 64, dense-synthesizer scores h @ w2t^T
    for (int k0 = 0; k0 < Hn; k0 += 8) {
        float4 av = *(const float4*)(Ah + (size_t)(bm + lrow) * Hn + k0 + lk);
        float4 bv = *(const float4*)(w2t + (size_t)(bn + lrow) * Hn + k0 + lk);
        As[lk + 0][lrow] = av.x; As[lk + 1][lrow] = av.y;
        As[lk + 2][lrow] = av.z; As[lk + 3][lrow] = av.w;
        Bs[lk + 0][lrow] = bv.x; Bs[lk + 1][lrow] = bv.y;
        Bs[lk + 2][lrow] = bv.z; Bs[lk + 3][lrow] = bv.w;
        __syncthreads();
        MMA_STEP();
        __syncthreads();
    }

#pragma unroll
    for (int i = 0; i < 8; ++i) {
        const int row = bm + ty * 8 + i;
#pragma unroll
        for (int j = 0; j < 8; ++j) {
            const int col = bn + tx * 8 + j;
            C[(size_t)row * Sn + col] = acc[i][j] + b2[col];
        }
    }
}

// ---------------- w2 [H,S] -> w2t [S,H] ------------------------------------
__global__ void transpose_w2(const float* __restrict__ w2, float* __restrict__ w2t)
{
    const int i = blockIdx.x * 256 + threadIdx.x;
    if (i < Sn * Hn) {
        const int t = i / Hn;
        const int e = i % Hn;
        w2t[i] = w2[e * Sn + t];
    }
}

// ---------------- in-place row softmax, optional copy to output -------------
__global__ void __launch_bounds__(256)
softmax_kernel(float* __restrict__ logits, float* __restrict__ attn_copy)
{
    const size_t row = blockIdx.x;
    float* rp = logits + row * Sn;
    const int tid = threadIdx.x;

    __shared__ float sd[8];

    float v[8];
    float mx = -CUDART_INF_F;
#pragma unroll
    for (int j = 0; j < 8; ++j) {
        v[j] = rp[tid + 256 * j];
        mx = fmaxf(mx, v[j]);
    }
#pragma unroll
    for (int o = 16; o; o >>= 1) mx = fmaxf(mx, __shfl_xor_sync(0xffffffffu, mx, o));
    if ((tid & 31) == 0) sd[tid >> 5] = mx;
    __syncthreads();
    if (tid < 32) {
        float x = (tid < 8) ? sd[tid] : -CUDART_INF_F;
#pragma unroll
        for (int o = 4; o; o >>= 1) x = fmaxf(x, __shfl_xor_sync(0xffffffffu, x, o));
        if (tid == 0) sd[0] = x;
    }
    __syncthreads();
    mx = sd[0];
    __syncthreads();

    float s = 0.f;
#pragma unroll
    for (int j = 0; j < 8; ++j) {
        v[j] = __expf(v[j] - mx);
        s += v[j];
    }
#pragma unroll
    for (int o = 16; o; o >>= 1) s += __shfl_xor_sync(0xffffffffu, s, o);
    if ((tid & 31) == 0) sd[tid >> 5] = s;
    __syncthreads();
    if (tid < 32) {
        float x = (tid < 8) ? sd[tid] : 0.f;
#pragma unroll
        for (int o = 4; o; o >>= 1) x += __shfl_xor_sync(0xffffffffu, x, o);
        if (tid == 0) sd[0] = x;
    }
    __syncthreads();
    const float inv = 1.f / sd[0];

#pragma unroll
    for (int j = 0; j < 8; ++j) {
        const float a = v[j] * inv;
        rp[tid + 256 * j] = a;
        if (attn_copy) attn_copy[row * Sn + tid + 256 * j] = a;
    }
}

// ---------------- launch -----------------------------------------------------
extern "C" void kernel_launch(void* const* d_in, const int* in_sizes, int n_in,
                              void* d_out_v, int out_size)
{
    (void)in_sizes; (void)n_in;
    const float* query = (const float*)d_in[0];
    const float* key   = (const float*)d_in[1];
    const float* value = (const float*)d_in[2];
    const float* w1    = (const float*)d_in[3];
    const float* b1    = (const float*)d_in[4];
    const float* w2    = (const float*)d_in[5];
    const float* b2    = (const float*)d_in[6];
    const float* wq    = (const float*)d_in[7];
    const float* bq    = (const float*)d_in[8];
    const float* wk    = (const float*)d_in[9];
    const float* bk    = (const float*)d_in[10];
    float* d_out = (float*)d_out_v;

    float *hbuf, *qbuf, *kbuf, *logits, *w2t;
    cudaGetSymbolAddress((void**)&hbuf,   g_h);
    cudaGetSymbolAddress((void**)&qbuf,   g_q);
    cudaGetSymbolAddress((void**)&kbuf,   g_k);
    cudaGetSymbolAddress((void**)&logits, g_logits);
    cudaGetSymbolAddress((void**)&w2t,    g_w2t);

    const long long BSD = (long long)Bn * Sn * Dn;  //  33,554,432
    const long long BSS = (long long)Bn * Sn * Sn;  //  67,108,864

    float* out_ptr  = nullptr;
    float* attn_ptr = nullptr;
    if ((long long)out_size == BSD + BSS) { out_ptr = d_out; attn_ptr = d_out + BSD; }
    else if ((long long)out_size == BSS)  { attn_ptr = d_out; }
    else                                  { out_ptr = d_out; }

    const int M = Bn * Sn;  // 32768

    // h = relu(query @ w1 + b1)            [M, 64]
    sgemm_nn<true, true><<<dim3(1, M / 128, 1), 256>>>(
        query, w1, b1, hbuf, M, Hn, Dn, 0, 0, 0);

    // q = query @ wq + bq                  [M, 1024]
    sgemm_nn<false, true><<<dim3(Dn / 128, M / 128, 1), 256>>>(
        query, wq, bq, qbuf, M, Dn, Dn, 0, 0, 0);

    // k = key @ wk + bk                    [M, 1024]
    sgemm_nn<false, true><<<dim3(Dn / 128, M / 128, 1), 256>>>(
        key, wk, bk, kbuf, M, Dn, Dn, 0, 0, 0);

    // w2t = w2^T                           [S, H]
    transpose_w2<<<(Sn * Hn + 255) / 256, 256>>>(w2, w2t);

    // logits = q@k^T + h@w2t^T + b2        [B, S, S]
    energy_kernel<<<dim3(Sn / 128, Sn / 128, Bn), 256>>>(
        qbuf, kbuf, hbuf, w2t, b2, logits);

    // attention = softmax(logits) (in place; optional copy to output)
    softmax_kernel<<<Bn * Sn, 256>>>(logits, attn_ptr);

    // out = attention @ value              [B, S, D]
    if (out_ptr) {
        sgemm_nn<false, false><<<dim3(Dn / 128, Sn / 128, Bn), 256>>>(
            logits, value, nullptr, out_ptr, Sn, Dn, Sn,
            (long long)Sn * Sn, (long long)Sn * Dn, (long long)Sn * Dn);
    }
}